// round 17
// baseline (speedup 1.0000x reference)
#include <cuda_runtime.h>
#include <cstdint>

#define BATCH   256
#define TSTEPS  1000
#define LIN     30
#define NCH     16
#define KW      7
#define LO      24
#define JDIM    384      // NCH*LO
#define NOUT    35
#define GR      12       // j-groups per output
#define JT      32       // j's per group
#define NTHREADS 384
#define CHUNK   50
#define NCHUNK  (TSTEPS / CHUNK)

typedef unsigned long long ull;

__device__ __forceinline__ uint32_t smem_u32(const void* p) {
    return (uint32_t)__cvta_generic_to_shared(p);
}
__device__ __forceinline__ void cp_async8(uint32_t dst, const void* src) {
    asm volatile("cp.async.ca.shared.global [%0], [%1], 8;" :: "r"(dst), "l"(src));
}
__device__ __forceinline__ void cp_commit() { asm volatile("cp.async.commit_group;"); }
__device__ __forceinline__ void cp_wait1()  { asm volatile("cp.async.wait_group 1;" ::: "memory"); }
__device__ __forceinline__ void cp_wait0()  { asm volatile("cp.async.wait_group 0;" ::: "memory"); }

__device__ __forceinline__ ull pk(float a, float b) {
    ull r; asm("mov.b64 %0, {%1,%2};" : "=l"(r) : "f"(a), "f"(b)); return r;
}
__device__ __forceinline__ void upk(ull v, float& a, float& b) {
    asm("mov.b64 {%0,%1}, %2;" : "=f"(a), "=f"(b) : "l"(v));
}
__device__ __forceinline__ ull f2fma(ull a, ull b, ull c) {
    ull d; asm("fma.rn.f32x2 %0, %1, %2, %3;" : "=l"(d) : "l"(a), "l"(b), "l"(c)); return d;
}

// One pipelined iteration: C(t-2), B(t-1), A(t); single barrier at the end.
// A writes spk[pa]; B reads spk[pa^1], writes part[pa^1]; C reads part[pa].
#define STEP(PA, XROW, DOA, DOB, DOC)                                          \
  {                                                                            \
    const int pa_ = (PA);                                                      \
    if ((DOC) && cTh) {                                                        \
      float c2 = part[pa_][0][ccol];                                           \
      _Pragma("unroll")                                                        \
      for (int rr = 1; rr < GR; ++rr) c2 += part[pa_][rr][ccol];               \
      c2 = __fadd_rn(c2, bias2);                                               \
      float r2 = (mem2 > 1.0f) ? 1.0f : 0.0f;                                  \
      mem2 = __fsub_rn(__fadd_rn(__fmul_rn(0.9f, mem2), c2), r2);              \
      acc += (double)mem2;                                                     \
    }                                                                          \
    if (DOB) {                                                                 \
      if (bmTh) { /* B-main: outputs om and om+16 from one spike stream */     \
        uint32_t sp = spkAddr + (uint32_t)((pa_ ^ 1) * (JDIM * 4));            \
        ull a0 = 0ull, a1 = 0ull, b0 = 0ull, b1 = 0ull;                        \
        _Pragma("unroll")                                                      \
        for (int k = 0; k < 16; k += 2) {                                      \
          ull s0, s1;                                                          \
          asm("ld.shared.v2.u64 {%0,%1}, [%2];"                                \
              : "=l"(s0), "=l"(s1) : "r"(sp + (uint32_t)(k * 8)));             \
          a0 = f2fma(s0, w2a[k],     a0);                                      \
          a1 = f2fma(s1, w2a[k + 1], a1);                                      \
          b0 = f2fma(s0, w2b[k],     b0);                                      \
          b1 = f2fma(s1, w2b[k + 1], b1);                                      \
        }                                                                      \
        float x0_, x1_, y0_, y1_, u0_, u1_, v0_, v1_;                          \
        upk(a0, x0_, x1_); upk(a1, y0_, y1_);                                  \
        upk(b0, u0_, u1_); upk(b1, v0_, v1_);                                  \
        part[pa_ ^ 1][brow][bcol]      = (x0_ + x1_) + (y0_ + y1_);            \
        part[pa_ ^ 1][brow][bcol + 16] = (u0_ + u1_) + (v0_ + v1_);            \
      } else if (beTh) { /* B-extra: single output 32..34 */                   \
        uint32_t sp = spkAddr + (uint32_t)((pa_ ^ 1) * (JDIM * 4));            \
        ull a0 = 0ull, a1 = 0ull;                                              \
        _Pragma("unroll")                                                      \
        for (int k = 0; k < 16; k += 2) {                                      \
          ull s0, s1;                                                          \
          asm("ld.shared.v2.u64 {%0,%1}, [%2];"                                \
              : "=l"(s0), "=l"(s1) : "r"(sp + (uint32_t)(k * 8)));             \
          a0 = f2fma(s0, w2a[k],     a0);                                      \
          a1 = f2fma(s1, w2a[k + 1], a1);                                      \
        }                                                                      \
        float x0_, x1_, y0_, y1_;                                              \
        upk(a0, x0_, x1_); upk(a1, y0_, y1_);                                  \
        part[pa_ ^ 1][brow][bcol] = (x0_ + x1_) + (y0_ + y1_);                 \
      }                                                                        \
    }                                                                          \
    if ((DOA) && aTh) {                                                        \
      const float2* xp = (const float2*)((XROW) + 4 * aq);                     \
      float xv[10];                                                            \
      _Pragma("unroll")                                                        \
      for (int i = 0; i < 5; ++i) {                                            \
        float2 f = xp[i];                                                      \
        xv[2 * i] = f.x; xv[2 * i + 1] = f.y;                                  \
      }                                                                        \
      float sp4[4];                                                            \
      _Pragma("unroll")                                                        \
      for (int d = 0; d < 4; ++d) {                                            \
        float s = __fmul_rn(xv[d], wc[0]);                                     \
        _Pragma("unroll")                                                      \
        for (int k = 1; k < KW; ++k) s = __fmaf_rn(xv[d + k], wc[k], s);       \
        float c1 = __fadd_rn(s, bc);                                           \
        float r1 = (m1[d] > 1.0f) ? 1.0f : 0.0f;                               \
        m1[d] = __fsub_rn(__fadd_rn(__fmul_rn(0.9f, m1[d]), c1), r1);          \
        sp4[d] = (m1[d] > 1.0f) ? 1.0f : 0.0f;                                 \
      }                                                                        \
      *(float4*)&spk[pa_][jA] = make_float4(sp4[0], sp4[1], sp4[2], sp4[3]);   \
    }                                                                          \
    __syncthreads();                                                           \
  }

__global__ __launch_bounds__(NTHREADS, 2)
void snn_kernel(const float* __restrict__ x,
                const float* __restrict__ conv_w,
                const float* __restrict__ conv_b,
                const float* __restrict__ fc_w,
                const float* __restrict__ fc_b,
                float* __restrict__ out)
{
    __shared__ __align__(16) float xs[2][CHUNK * LIN + 2];  // 12 KB double-buffered x
    __shared__ __align__(16) float spk[2][JDIM];            // double-buffered spikes (f32)
    __shared__ float part[2][GR][40];                       // double-buffered FC partials

    const int b   = blockIdx.x;
    const int tid = threadIdx.x;

    // ---- Role map ----
    // B-main : tid 0-191   -> (r = tid>>4, o = tid&15) computes outputs o, o+16
    // B-extra: tid 192-223 -> i = tid-192 ; tid 320-323 -> i = tid-288 ; (r=i/3, o=32+i%3)
    // A      : tid 224-319 -> a = tid-224, ch = a/6, q = a%6, positions 4q..4q+3
    // C      : tid 324-358 -> ccol = tid-324
    const bool bmTh = (tid < 192);
    const bool beTh = (tid >= 192 && tid < 224) || (tid >= 320 && tid < 324);
    const bool aTh  = (tid >= 224 && tid < 320);
    const bool cTh  = (tid >= 324 && tid < 324 + NOUT);

    // ---- B state ----
    int brow = 0, bcol = 0;
    if (bmTh)      { brow = tid >> 4;  bcol = tid & 15; }
    else if (beTh) { int i = (tid < 224) ? (tid - 192) : (tid - 288);
                     brow = i / 3; bcol = 32 + i % 3; }
    ull w2a[16], w2b[16];
    if (bmTh || beTh) {
        #pragma unroll
        for (int k = 0; k < 16; ++k)
            w2a[k] = pk(fc_w[bcol * JDIM + brow * JT + 2 * k],
                        fc_w[bcol * JDIM + brow * JT + 2 * k + 1]);
    }
    if (bmTh) {
        #pragma unroll
        for (int k = 0; k < 16; ++k)
            w2b[k] = pk(fc_w[(bcol + 16) * JDIM + brow * JT + 2 * k],
                        fc_w[(bcol + 16) * JDIM + brow * JT + 2 * k + 1]);
    }
    const uint32_t spkAddr = smem_u32(&spk[0][0]) + (uint32_t)(brow * JT * 4);

    // ---- A state: 4 positions (4q..4q+3) of channel ch ----
    const int aidx = tid - 224;
    const int ach  = aidx / 6;
    const int aq   = aidx % 6;
    const int jA   = ach * LO + 4 * aq;
    float wc[KW], bc = 0.f;
    float m1[4] = {0.f, 0.f, 0.f, 0.f};
    if (aTh) {
        #pragma unroll
        for (int k = 0; k < KW; ++k) wc[k] = conv_w[ach * KW + k];
        bc = conv_b[ach];
    }

    // ---- C state ----
    const int ccol = tid - 324;
    float  bias2 = 0.f, mem2 = 0.f;
    double acc   = 0.0;
    if (cTh) bias2 = fc_b[ccol];

    const float* xb = x + (size_t)b * TSTEPS * LIN;

    // ---- prefetch chunk 0 (750 x 8B over 384 threads) ----
    {
        uint32_t sbase = smem_u32(&xs[0][0]);
        for (int i = tid; i < CHUNK * LIN / 2; i += NTHREADS)
            cp_async8(sbase + i * 8, xb + i * 2);
        cp_commit();
    }

    for (int chunk = 0; chunk < NCHUNK; ++chunk) {
        const int buf = chunk & 1;
        if (chunk + 1 < NCHUNK) {
            uint32_t sbase   = smem_u32(&xs[buf ^ 1][0]);
            const float* src = xb + (size_t)(chunk + 1) * CHUNK * LIN;
            for (int i = tid; i < CHUNK * LIN / 2; i += NTHREADS)
                cp_async8(sbase + i * 8, src + i * 2);
            cp_commit();
            cp_wait1();
        } else {
            cp_wait0();
        }
        __syncthreads();

        const float* xrow = &xs[buf][0];
        if (chunk == 0) {
            // fill: B off at tc=0, C off at tc<2
            #pragma unroll 2
            for (int tc = 0; tc < CHUNK; ++tc)
                STEP(tc & 1, xrow + tc * LIN, true, tc >= 1, tc >= 2);
        } else {
            // steady state (CHUNK even -> parity = tc&1 every chunk)
            #pragma unroll 2
            for (int tc = 0; tc < CHUNK; ++tc)
                STEP(tc & 1, xrow + tc * LIN, true, true, true);
        }
    }

    // ---- drain: t=1000 (B(999), C(998)); t=1001 (C(999)) ----
    STEP(0, &xs[0][0], false, true, true);
    STEP(1, &xs[0][0], false, false, true);

    if (cTh)
        out[b * NOUT + ccol] = (float)(acc * (1.0 / (double)TSTEPS));
}

extern "C" void kernel_launch(void* const* d_in, const int* in_sizes, int n_in,
                              void* d_out, int out_size)
{
    const float* x      = (const float*)d_in[0];
    const float* conv_w = (const float*)d_in[1];
    const float* conv_b = (const float*)d_in[2];
    const float* fc_w   = (const float*)d_in[3];
    const float* fc_b   = (const float*)d_in[4];
    snn_kernel<<<BATCH, NTHREADS>>>(x, conv_w, conv_b, fc_w, fc_b, (float*)d_out);
}